// round 1
// baseline (speedup 1.0000x reference)
#include <cuda_runtime.h>

#define NPTS   16384
#define TPB    256
#define QPT    2                    // queries per thread
#define QCHUNK (TPB * QPT)          // 512 queries per block
#define NCHUNK (NPTS / QCHUNK)      // 32
#define SEGS   16
#define SEGLEN (NPTS / SEGS)        // 1024 refs per segment

// Scratch (static device globals — no allocation in kernel_launch).
// g_ref[0] = packed target (refs for pass 0: queries=predict)
// g_ref[1] = packed predict (refs for pass 1: queries=target)
__device__ float4       g_ref[2][NPTS];
__device__ unsigned int g_minbits[2][NPTS];

// Order-preserving float <-> uint mapping (works for negatives):
// min over floats == min over flipped uints.
__device__ __forceinline__ unsigned int fflip(float f) {
    unsigned int u = __float_as_uint(f);
    return (u & 0x80000000u) ? ~u : (u | 0x80000000u);
}
__device__ __forceinline__ float funflip(unsigned int u) {
    u = (u & 0x80000000u) ? (u ^ 0x80000000u) : ~u;
    return __uint_as_float(u);
}

__global__ void chamfer_prep(const float* __restrict__ pr,
                             const float* __restrict__ tg) {
    int i = blockIdx.x * blockDim.x + threadIdx.x;
    if (i >= NPTS) return;
    float x = tg[3 * i], y = tg[3 * i + 1], z = tg[3 * i + 2];
    g_ref[0][i] = make_float4(x, y, z, 0.5f * (x * x + y * y + z * z));
    x = pr[3 * i]; y = pr[3 * i + 1]; z = pr[3 * i + 2];
    g_ref[1][i] = make_float4(x, y, z, 0.5f * (x * x + y * y + z * z));
    g_minbits[0][i] = 0xFFFFFFFFu;   // flip(+inf) region: max uint
    g_minbits[1][i] = 0xFFFFFFFFu;
}

// One block: 512 queries x one 1024-ref segment. blockIdx.z = pass.
// Thread-local min of e = 0.5|t|^2 - q.t over the segment, merged with
// atomicMin on flipped bits.
__global__ void __launch_bounds__(TPB)
chamfer_pass(const float* __restrict__ pr, const float* __restrict__ tg) {
    const int pass = blockIdx.z;
    const float* __restrict__ qsrc = (pass == 0) ? pr : tg;
    const float4* __restrict__ ref = g_ref[pass];

    __shared__ float4 sref[SEGLEN];

    const int segBase = blockIdx.y * SEGLEN;
#pragma unroll
    for (int j = threadIdx.x; j < SEGLEN; j += TPB)
        sref[j] = ref[segBase + j];

    const int q0 = blockIdx.x * QCHUNK + threadIdx.x;
    const int q1 = q0 + TPB;
    // negated query coords so e = fma(nq, t, 0.5*t2) chains cleanly
    const float nx0 = -qsrc[3 * q0], ny0 = -qsrc[3 * q0 + 1], nz0 = -qsrc[3 * q0 + 2];
    const float nx1 = -qsrc[3 * q1], ny1 = -qsrc[3 * q1 + 1], nz1 = -qsrc[3 * q1 + 2];

    __syncthreads();

    const float INF = __int_as_float(0x7f800000);
    float m00 = INF, m01 = INF;   // query0: two accumulators (break FMNMX chain)
    float m10 = INF, m11 = INF;   // query1

#pragma unroll 4
    for (int j = 0; j < SEGLEN; j += 2) {
        float4 r = sref[j];
        float e0 = __fmaf_rn(nx0, r.x, r.w);
        e0 = __fmaf_rn(ny0, r.y, e0);
        e0 = __fmaf_rn(nz0, r.z, e0);
        float e1 = __fmaf_rn(nx1, r.x, r.w);
        e1 = __fmaf_rn(ny1, r.y, e1);
        e1 = __fmaf_rn(nz1, r.z, e1);
        m00 = fminf(m00, e0);
        m10 = fminf(m10, e1);

        float4 s = sref[j + 1];
        float f0 = __fmaf_rn(nx0, s.x, s.w);
        f0 = __fmaf_rn(ny0, s.y, f0);
        f0 = __fmaf_rn(nz0, s.z, f0);
        float f1 = __fmaf_rn(nx1, s.x, s.w);
        f1 = __fmaf_rn(ny1, s.y, f1);
        f1 = __fmaf_rn(nz1, s.z, f1);
        m01 = fminf(m01, f0);
        m11 = fminf(m11, f1);
    }

    float m0 = fminf(m00, m01);
    float m1 = fminf(m10, m11);
    atomicMin(&g_minbits[pass][q0], fflip(m0));
    atomicMin(&g_minbits[pass][q1], fflip(m1));
}

// d_q = max(2*min_e + |q|^2, 0);  loss = (sum_pass0 + sum_pass1) / NPTS
__global__ void __launch_bounds__(TPB)
chamfer_reduce(const float* __restrict__ pr, const float* __restrict__ tg,
               float* __restrict__ out) {
    __shared__ float sh[TPB];
    float s = 0.0f;
    for (int i = threadIdx.x; i < NPTS; i += TPB) {
        float x = pr[3 * i], y = pr[3 * i + 1], z = pr[3 * i + 2];
        float q2 = x * x + y * y + z * z;
        float d = __fmaf_rn(2.0f, funflip(g_minbits[0][i]), q2);
        s += fmaxf(d, 0.0f);

        x = tg[3 * i]; y = tg[3 * i + 1]; z = tg[3 * i + 2];
        q2 = x * x + y * y + z * z;
        d = __fmaf_rn(2.0f, funflip(g_minbits[1][i]), q2);
        s += fmaxf(d, 0.0f);
    }
    sh[threadIdx.x] = s;
    __syncthreads();
#pragma unroll
    for (int off = TPB / 2; off > 0; off >>= 1) {
        if (threadIdx.x < off) sh[threadIdx.x] += sh[threadIdx.x + off];
        __syncthreads();
    }
    if (threadIdx.x == 0)
        out[0] = sh[0] * (1.0f / (float)NPTS);
}

extern "C" void kernel_launch(void* const* d_in, const int* in_sizes, int n_in,
                              void* d_out, int out_size) {
    const float* pr = (const float*)d_in[0];   // predict [1,16384,3]
    const float* tg = (const float*)d_in[1];   // target  [1,16384,3]
    float* out = (float*)d_out;

    chamfer_prep<<<(NPTS + TPB - 1) / TPB, TPB>>>(pr, tg);

    dim3 grid(NCHUNK, SEGS, 2);
    chamfer_pass<<<grid, TPB>>>(pr, tg);

    chamfer_reduce<<<1, TPB>>>(pr, tg, out);
}

// round 2
// speedup vs baseline: 1.1503x; 1.1503x over previous
#include <cuda_runtime.h>

#define NPTS   16384
#define TPB    256
#define QPT    4                    // queries per thread
#define QCHUNK (TPB * QPT)          // 1024 queries per block
#define NCHUNK (NPTS / QCHUNK)      // 16
#define SEGS   32
#define SEGLEN (NPTS / SEGS)        // 512 refs per segment
#define SEGP   (SEGLEN / 2)         // 256 packed ref-pairs per segment

typedef unsigned long long u64;
typedef unsigned int       u32;

// Packed-pair SoA refs: g_x[p][j] = {x_{2j}, x_{2j+1}} etc. w = 0.5*|t|^2.
// p=0: refs = target (queries = predict). p=1: refs = predict.
__device__ float2 g_x[2][NPTS / 2];
__device__ float2 g_y[2][NPTS / 2];
__device__ float2 g_z[2][NPTS / 2];
__device__ float2 g_w[2][NPTS / 2];
__device__ u32    g_minbits[2][NPTS];

// ---- packed f32x2 helpers ----
__device__ __forceinline__ u64 pack2(float lo, float hi) {
    u64 r;
    asm("mov.b64 %0, {%1, %2};" : "=l"(r) : "f"(lo), "f"(hi));
    return r;
}
__device__ __forceinline__ float2 unpack2(u64 v) {
    float2 r;
    asm("mov.b64 {%0, %1}, %2;" : "=f"(r.x), "=f"(r.y) : "l"(v));
    return r;
}
__device__ __forceinline__ u64 fma2(u64 a, u64 b, u64 c) {
    u64 d;
    asm("fma.rn.f32x2 %0, %1, %2, %3;" : "=l"(d) : "l"(a), "l"(b), "l"(c));
    return d;
}

// Order-preserving float <-> uint flip (min over floats == min over flipped uints)
__device__ __forceinline__ u32 fflip(float f) {
    u32 u = __float_as_uint(f);
    return (u & 0x80000000u) ? ~u : (u | 0x80000000u);
}
__device__ __forceinline__ float funflip(u32 u) {
    u = (u & 0x80000000u) ? (u ^ 0x80000000u) : ~u;
    return __uint_as_float(u);
}

__global__ void chamfer_prep(const float* __restrict__ pr,
                             const float* __restrict__ tg) {
    int i = blockIdx.x * blockDim.x + threadIdx.x;
    if (i >= NPTS / 2) return;
    int a = 2 * i, b = 2 * i + 1;

    float ax = tg[3 * a], ay = tg[3 * a + 1], az = tg[3 * a + 2];
    float bx = tg[3 * b], by = tg[3 * b + 1], bz = tg[3 * b + 2];
    g_x[0][i] = make_float2(ax, bx);
    g_y[0][i] = make_float2(ay, by);
    g_z[0][i] = make_float2(az, bz);
    g_w[0][i] = make_float2(0.5f * (ax * ax + ay * ay + az * az),
                            0.5f * (bx * bx + by * by + bz * bz));

    ax = pr[3 * a]; ay = pr[3 * a + 1]; az = pr[3 * a + 2];
    bx = pr[3 * b]; by = pr[3 * b + 1]; bz = pr[3 * b + 2];
    g_x[1][i] = make_float2(ax, bx);
    g_y[1][i] = make_float2(ay, by);
    g_z[1][i] = make_float2(az, bz);
    g_w[1][i] = make_float2(0.5f * (ax * ax + ay * ay + az * az),
                            0.5f * (bx * bx + by * by + bz * bz));

    g_minbits[0][a] = 0xFFFFFFFFu; g_minbits[0][b] = 0xFFFFFFFFu;
    g_minbits[1][a] = 0xFFFFFFFFu; g_minbits[1][b] = 0xFFFFFFFFu;
}

// One block: QCHUNK queries x one SEGLEN-ref segment, refs packed in pairs.
// e = 0.5|t|^2 - q.t computed 2-wide via fma.rn.f32x2; per-query min merged
// into g_minbits with atomicMin on flipped bits.
__global__ void __launch_bounds__(TPB)
chamfer_pass(const float* __restrict__ pr, const float* __restrict__ tg) {
    const int pass = blockIdx.z;
    const float* __restrict__ qsrc = (pass == 0) ? pr : tg;

    __shared__ float2 sx[SEGP], sy[SEGP], sz[SEGP], sw[SEGP];

    const int segBase = blockIdx.y * SEGP;   // in packed-pair units
    {
        int j = threadIdx.x;                  // SEGP == TPB
        sx[j] = g_x[pass][segBase + j];
        sy[j] = g_y[pass][segBase + j];
        sz[j] = g_z[pass][segBase + j];
        sw[j] = g_w[pass][segBase + j];
    }

    const int qb = blockIdx.x * QCHUNK + threadIdx.x;
    u64 nx[QPT], ny[QPT], nz[QPT];
#pragma unroll
    for (int k = 0; k < QPT; k++) {
        int q = qb + k * TPB;
        float x = -qsrc[3 * q], y = -qsrc[3 * q + 1], z = -qsrc[3 * q + 2];
        nx[k] = pack2(x, x);
        ny[k] = pack2(y, y);
        nz[k] = pack2(z, z);
    }

    __syncthreads();

    const float INF = __int_as_float(0x7f800000);
    float mlo[QPT], mhi[QPT];
#pragma unroll
    for (int k = 0; k < QPT; k++) { mlo[k] = INF; mhi[k] = INF; }

#pragma unroll 4
    for (int j = 0; j < SEGP; j++) {
        u64 X = pack2(sx[j].x, sx[j].y);
        u64 Y = pack2(sy[j].x, sy[j].y);
        u64 Z = pack2(sz[j].x, sz[j].y);
        u64 W = pack2(sw[j].x, sw[j].y);
#pragma unroll
        for (int k = 0; k < QPT; k++) {
            u64 e = fma2(nx[k], X, W);
            e = fma2(ny[k], Y, e);
            e = fma2(nz[k], Z, e);
            float2 ef = unpack2(e);
            mlo[k] = fminf(mlo[k], ef.x);
            mhi[k] = fminf(mhi[k], ef.y);
        }
    }

#pragma unroll
    for (int k = 0; k < QPT; k++) {
        float m = fminf(mlo[k], mhi[k]);
        atomicMin(&g_minbits[pass][qb + k * TPB], fflip(m));
    }
}

// d_q = max(2*min_e + |q|^2, 0);  loss = (sum_pass0 + sum_pass1) / NPTS
__global__ void __launch_bounds__(TPB)
chamfer_reduce(const float* __restrict__ pr, const float* __restrict__ tg,
               float* __restrict__ out) {
    __shared__ float sh[TPB];
    float s = 0.0f;
    for (int i = threadIdx.x; i < NPTS; i += TPB) {
        float x = pr[3 * i], y = pr[3 * i + 1], z = pr[3 * i + 2];
        float q2 = x * x + y * y + z * z;
        float d = __fmaf_rn(2.0f, funflip(g_minbits[0][i]), q2);
        s += fmaxf(d, 0.0f);

        x = tg[3 * i]; y = tg[3 * i + 1]; z = tg[3 * i + 2];
        q2 = x * x + y * y + z * z;
        d = __fmaf_rn(2.0f, funflip(g_minbits[1][i]), q2);
        s += fmaxf(d, 0.0f);
    }
    sh[threadIdx.x] = s;
    __syncthreads();
#pragma unroll
    for (int off = TPB / 2; off > 0; off >>= 1) {
        if (threadIdx.x < off) sh[threadIdx.x] += sh[threadIdx.x + off];
        __syncthreads();
    }
    if (threadIdx.x == 0)
        out[0] = sh[0] * (1.0f / (float)NPTS);
}

extern "C" void kernel_launch(void* const* d_in, const int* in_sizes, int n_in,
                              void* d_out, int out_size) {
    const float* pr = (const float*)d_in[0];   // predict [1,16384,3]
    const float* tg = (const float*)d_in[1];   // target  [1,16384,3]
    float* out = (float*)d_out;

    chamfer_prep<<<(NPTS / 2 + TPB - 1) / TPB, TPB>>>(pr, tg);

    dim3 grid(NCHUNK, SEGS, 2);
    chamfer_pass<<<grid, TPB>>>(pr, tg);

    chamfer_reduce<<<1, TPB>>>(pr, tg, out);
}